// round 1
// baseline (speedup 1.0000x reference)
#include <cuda_runtime.h>

#define BATCH  64
#define NTOK   577
#define PTOK   576      // patches
#define DENS   288      // kept dense tokens
#define SSZ    288      // skipped tokens
#define GSZ    144      // selected group size
#define DIM    768
#define OUTROWS 433     // 1 + DENS + GSZ
#define RCOLS  432      // DENS + GSZ
#define EMAX   1200     // <= 4*288 = 1152 edges max

// ---------------- scratch (device globals; no allocation) ----------------
__device__ int   g_rowmap[BATCH][OUTROWS];      // attention/tk row index per output row
__device__ int   g_colmap[BATCH][RCOLS];        // attention col index per R column
__device__ int   g_ein[BATCH][EMAX];            // tk row index of edge source (1+order[288+i])
__device__ float g_ew[BATCH][EMAX];             // edge weight, 0 if pruned
__device__ int   g_selrange[BATCH][GSZ][2];     // CSR [start,end) of incoming edges per selected node

// ---------------- kernel 1: per-batch graph build + prune -----------------
__global__ __launch_bounds__(288) void k_graph(const float* __restrict__ attn) {
    const int b   = blockIdx.x;
    const int tid = threadIdx.x;                 // 288 threads
    const float* A0 = attn + (size_t)b * NTOK * PTOK;

    __shared__ float a[PTOK];
    __shared__ int   order[PTOK];
    __shared__ unsigned bits[SSZ * 9];           // 288x288 bit adjacency
    __shared__ int   t2[SSZ * 2];
    __shared__ int   cnt[SSZ];
    __shared__ int   offs[SSZ + 1];
    __shared__ int   ein[EMAX];
    __shared__ float ew[EMAX];
    __shared__ unsigned char alive[EMAX];
    __shared__ float favg[SSZ];
    __shared__ int   degi[SSZ];
    __shared__ int   gsel[GSZ];
    __shared__ int   changed;

    // cls attention row
    for (int p = tid; p < PTOK; p += 288) a[p] = A0[p];
    __syncthreads();

    // order = argsort(-a), stable (ties -> smaller index first)
    for (int p = tid; p < PTOK; p += 288) {
        float v = a[p];
        int r = 0;
        for (int q = 0; q < PTOK; q++) {
            float u = a[q];
            r += (u > v) || (u == v && q < p);
        }
        order[r] = p;
    }
    for (int k = tid; k < SSZ * 9; k += 288) bits[k] = 0;
    __syncthreads();

    // top-2 per row of permuted skip attention (diag excluded)
    {
        const int i = tid;
        const int ri = 1 + order[DENS + i];
        const float* row = A0 + (size_t)ri * PTOK;
        float v1 = -1.f, v2 = -1.f;
        int j1 = -1, j2 = -1;
        for (int j = 0; j < SSZ; j++) {
            if (j == i) continue;
            float v = row[order[DENS + j]];
            if (v > v1)      { v2 = v1; j2 = j1; v1 = v; j1 = j; }
            else if (v > v2) { v2 = v;  j2 = j; }
        }
        t2[i * 2] = j1; t2[i * 2 + 1] = j2;
    }
    __syncthreads();

    // symmetrize: bit(i,j) if j in top2(i) or i in top2(j)
    {
        const int i = tid;
        const int j1 = t2[i * 2], j2 = t2[i * 2 + 1];
        atomicOr(&bits[i * 9 + (j1 >> 5)], 1u << (j1 & 31));
        atomicOr(&bits[i * 9 + (j2 >> 5)], 1u << (j2 & 31));
        atomicOr(&bits[j1 * 9 + (i >> 5)], 1u << (i & 31));
        atomicOr(&bits[j2 * 9 + (i >> 5)], 1u << (i & 31));
    }
    __syncthreads();

    // incoming-degree counts per column j
    {
        const int j = tid;
        const unsigned m = 1u << (j & 31);
        const int w = j >> 5;
        int c = 0;
        for (int i = 0; i < SSZ; i++) c += (bits[i * 9 + w] & m) ? 1 : 0;
        cnt[j] = c;
    }
    __syncthreads();
    if (tid == 0) {
        int acc = 0;
        for (int j = 0; j < SSZ; j++) { offs[j] = acc; acc += cnt[j]; }
        offs[SSZ] = acc;
    }
    __syncthreads();

    // fill incoming CSR (i ascending within each j). M = (W != 0)
    {
        const int j = tid;
        const unsigned m = 1u << (j & 31);
        const int w = j >> 5;
        const int cj = order[DENS + j];
        int ptr = offs[j];
        for (int i = 0; i < SSZ; i++) {
            if (bits[i * 9 + w] & m) {
                float wv = A0[(size_t)(1 + order[DENS + i]) * PTOK + cj];
                ein[ptr] = i;
                ew[ptr]  = wv;
                alive[ptr] = (wv != 0.f) ? 1 : 0;
                ptr++;
            }
        }
    }

    // fixed-point pruning: m <- m & (avg[j] > avg[i])
    for (;;) {
        __syncthreads();
        {
            const int j = tid;
            int dg = 0; float s = 0.f;
            for (int e = offs[j]; e < offs[j + 1]; e++)
                if (alive[e]) { dg++; s += ew[e]; }
            degi[j] = dg;
            favg[j] = (dg > 0) ? (s / (float)dg) : 0.f;
        }
        if (tid == 0) changed = 0;
        __syncthreads();
        {
            const int j = tid;
            const float aj = favg[j];
            int ch = 0;
            for (int e = offs[j]; e < offs[j + 1]; e++)
                if (alive[e] && !(aj > favg[ein[e]])) { alive[e] = 0; ch = 1; }
            if (ch) atomicExch(&changed, 1);
        }
        __syncthreads();
        if (!changed) break;
    }

    // zero pruned weights
    {
        const int j = tid;
        for (int e = offs[j]; e < offs[j + 1]; e++)
            if (!alive[e]) ew[e] = 0.f;
    }

    // top-144 by in-degree (ties -> smaller index first)
    {
        const int j = tid;
        const int dj = degi[j];
        int r = 0;
        for (int q = 0; q < SSZ; q++) {
            int dq = degi[q];
            r += (dq > dj) || (dq == dj && q < j);
        }
        if (r < GSZ) gsel[r] = j;
    }
    __syncthreads();

    // ---- write scratch to global ----
    for (int e = tid; e < offs[SSZ]; e += 288) {
        g_ein[b][e] = 1 + order[DENS + ein[e]];   // resolve to tk row index
        g_ew[b][e]  = ew[e];
    }
    for (int g = tid; g < GSZ; g += 288) {
        int j = gsel[g];
        g_selrange[b][g][0] = offs[j];
        g_selrange[b][g][1] = offs[j + 1];
    }
    for (int u = tid; u < OUTROWS; u += 288) {
        int row;
        if (u == 0)            row = 0;
        else if (u <= DENS)    row = 1 + order[u - 1];
        else                   row = 1 + order[DENS + gsel[u - 1 - DENS]];
        g_rowmap[b][u] = row;
    }
    for (int v = tid; v < RCOLS; v += 288) {
        int c;
        if (v < DENS) c = order[v];
        else          c = order[DENS + gsel[v - DENS]];
        g_colmap[b][v] = c;
    }
}

// ---------------- kernel 2: out_tokens [B,433,768] ------------------------
__global__ __launch_bounds__(192) void k_tokens(const float* __restrict__ tk,
                                                float* __restrict__ out) {
    const int u = blockIdx.x;
    const int b = blockIdx.y;
    const int t = threadIdx.x;                   // 192 threads -> float4 over 768
    const float4* tk4 = (const float4*)tk;
    const int row = g_rowmap[b][u];
    float4 v = tk4[((size_t)b * NTOK + row) * (DIM / 4) + t];

    if (u > DENS) {                              // aggregated skip-selected rows
        const int g = u - 1 - DENS;
        const int st = g_selrange[b][g][0];
        const int en = g_selrange[b][g][1];
        float4 acc = make_float4(0.f, 0.f, 0.f, 0.f);
        for (int e = st; e < en; e++) {
            float w = g_ew[b][e];
            if (w != 0.f) {
                int sr = g_ein[b][e];
                float4 sv = tk4[((size_t)b * NTOK + sr) * (DIM / 4) + t];
                acc.x += w * sv.x; acc.y += w * sv.y;
                acc.z += w * sv.z; acc.w += w * sv.w;
            }
        }
        v.x = acc.x + v.x; v.y = acc.y + v.y;
        v.z = acc.z + v.z; v.w = acc.w + v.w;
    }
    ((float4*)out)[((size_t)b * OUTROWS + u) * (DIM / 4) + t] = v;
}

// ---------------- kernel 3: R [B,433,432] ----------------------------------
__global__ __launch_bounds__(192) void k_R(const float* __restrict__ attn,
                                           float* __restrict__ out) {
    __shared__ float srow[PTOK];
    __shared__ int   cmap[RCOLS];
    const int u = blockIdx.x;
    const int b = blockIdx.y;
    const int t = threadIdx.x;
    const int arow = g_rowmap[b][u];
    const float* src = attn + ((size_t)b * NTOK + arow) * PTOK;
    for (int p = t; p < PTOK; p += 192) srow[p] = src[p];
    for (int v = t; v < RCOLS; v += 192) cmap[v] = g_colmap[b][v];
    __syncthreads();
    float* dst = out + (size_t)BATCH * OUTROWS * DIM
                     + ((size_t)b * OUTROWS + u) * RCOLS;
    for (int v = t; v < RCOLS; v += 192) dst[v] = srow[cmap[v]];
}

// ---------------- launch ---------------------------------------------------
extern "C" void kernel_launch(void* const* d_in, const int* in_sizes, int n_in,
                              void* d_out, int out_size) {
    const float* tk   = (const float*)d_in[0];
    const float* attn = (const float*)d_in[1];
    float* out = (float*)d_out;

    k_graph <<<BATCH, 288>>>(attn);
    k_tokens<<<dim3(OUTROWS, BATCH), 192>>>(tk, out);
    k_R     <<<dim3(OUTROWS, BATCH), 192>>>(attn, out);
}

// round 2
// speedup vs baseline: 1.8178x; 1.8178x over previous
#include <cuda_runtime.h>

#define BATCH  64
#define NTOK   577
#define PTOK   576      // patches
#define DENS   288      // kept dense tokens
#define SSZ    288      // skipped tokens
#define GSZ    144      // selected group size
#define DIM    768
#define OUTROWS 433     // 1 + DENS + GSZ
#define RCOLS  432      // DENS + GSZ
#define EMAX   1200     // <= 4*288 = 1152 edges max

// ---------------- scratch (device globals; no allocation) ----------------
__device__ int   g_order[BATCH][PTOK];          // argsort(-cls_attn)
__device__ int   g_t2[BATCH][SSZ][2];           // top-2 neighbor per skip row
__device__ int   g_rowmap[BATCH][OUTROWS];      // attention/tk row index per output row
__device__ int   g_colmap[BATCH][RCOLS];        // attention col index per R column
__device__ int   g_ein[BATCH][EMAX];            // tk row index of edge source
__device__ float g_ew[BATCH][EMAX];             // edge weight, 0 if pruned
__device__ int   g_selrange[BATCH][GSZ][2];     // CSR [start,end) per selected node

// ---------------- kernel A: argsort(-cls_attn), stable ---------------------
__global__ __launch_bounds__(PTOK) void k_order(const float* __restrict__ attn) {
    const int b = blockIdx.x;
    const int p = threadIdx.x;                  // one thread per element
    __shared__ float a[PTOK];
    __shared__ int   ord[PTOK];
    a[p] = attn[(size_t)b * NTOK * PTOK + p];
    __syncthreads();
    const float v = a[p];
    int r = 0;
    #pragma unroll 8
    for (int q = 0; q < PTOK; q++) {
        float u = a[q];
        r += (u > v) || (u == v && q < p);
    }
    ord[r] = p;
    __syncthreads();
    g_order[b][p] = ord[p];
}

// ---------------- kernel B: top-2 per skip row (1 warp per row) ------------
__global__ __launch_bounds__(128) void k_top2(const float* __restrict__ attn) {
    const int b    = blockIdx.y;
    const int warp = threadIdx.x >> 5;
    const int lane = threadIdx.x & 31;
    const int i    = blockIdx.x * 4 + warp;     // skip row index 0..287

    __shared__ int   ords[SSZ];
    __shared__ float rows[4][PTOK];

    for (int j = threadIdx.x; j < SSZ; j += 128) ords[j] = g_order[b][DENS + j];
    __syncthreads();

    const int ri = 1 + ords[i];
    const float* src = attn + ((size_t)b * NTOK + ri) * PTOK;
    for (int p = lane; p < PTOK; p += 32) rows[warp][p] = src[p];
    __syncwarp();

    // local top-2 with key = (monotone(value), 287-j): tie -> smaller j wins
    unsigned long long k1 = 0ull, k2 = 0ull;
    for (int j = lane; j < SSZ; j += 32) {
        if (j == i) continue;
        float v = rows[warp][ords[j]];
        unsigned ub = __float_as_uint(v);
        ub ^= (unsigned)(((int)ub >> 31)) | 0x80000000u;   // total order on floats
        unsigned long long key = ((unsigned long long)ub << 32) | (unsigned)(SSZ - 1 - j);
        if (key > k1)      { k2 = k1; k1 = key; }
        else if (key > k2) { k2 = key; }
    }
    // warp reduce merged top-2
    #pragma unroll
    for (int off = 16; off > 0; off >>= 1) {
        unsigned long long o1 = __shfl_down_sync(0xffffffffu, k1, off);
        unsigned long long o2 = __shfl_down_sync(0xffffffffu, k2, off);
        if (o1 > k1) { k2 = (k1 > o2) ? k1 : o2; k1 = o1; }
        else         { k2 = (k2 > o1) ? k2 : o1; }
    }
    if (lane == 0) {
        g_t2[b][i][0] = SSZ - 1 - (int)(k1 & 0xffffffffu);
        g_t2[b][i][1] = SSZ - 1 - (int)(k2 & 0xffffffffu);
    }
}

// ---------------- kernel C: symmetrize + CSR + prune + select --------------
__global__ __launch_bounds__(288) void k_graph2(const float* __restrict__ attn) {
    const int b   = blockIdx.x;
    const int tid = threadIdx.x;                 // 288 threads
    const float* A0 = attn + (size_t)b * NTOK * PTOK;

    __shared__ int   order[PTOK];
    __shared__ unsigned bits[SSZ * 9];           // 288x288 bit adjacency
    __shared__ int   cnt[SSZ];
    __shared__ int   offs[SSZ + 1];
    __shared__ int   ein[EMAX];
    __shared__ float ew[EMAX];
    __shared__ unsigned char alive[EMAX];
    __shared__ float favg[SSZ];
    __shared__ int   degi[SSZ];
    __shared__ int   gsel[GSZ];
    __shared__ int   changed;

    for (int p = tid; p < PTOK; p += 288) order[p] = g_order[b][p];
    for (int k = tid; k < SSZ * 9; k += 288) bits[k] = 0;
    __syncthreads();

    // symmetrize: bit(i,j) if j in top2(i) or i in top2(j)
    {
        const int i = tid;
        const int j1 = g_t2[b][i][0], j2 = g_t2[b][i][1];
        atomicOr(&bits[i * 9 + (j1 >> 5)], 1u << (j1 & 31));
        atomicOr(&bits[i * 9 + (j2 >> 5)], 1u << (j2 & 31));
        atomicOr(&bits[j1 * 9 + (i >> 5)], 1u << (i & 31));
        atomicOr(&bits[j2 * 9 + (i >> 5)], 1u << (i & 31));
    }
    __syncthreads();

    // incoming-degree counts per column j
    {
        const int j = tid;
        const unsigned m = 1u << (j & 31);
        const int w = j >> 5;
        int c = 0;
        for (int i = 0; i < SSZ; i++) c += (bits[i * 9 + w] & m) ? 1 : 0;
        cnt[j] = c;
    }
    __syncthreads();
    if (tid == 0) {
        int acc = 0;
        for (int j = 0; j < SSZ; j++) { offs[j] = acc; acc += cnt[j]; }
        offs[SSZ] = acc;
    }
    __syncthreads();

    // fill incoming CSR (i ascending within each j). M = (W != 0)
    {
        const int j = tid;
        const unsigned m = 1u << (j & 31);
        const int w = j >> 5;
        const int cj = order[DENS + j];
        int ptr = offs[j];
        for (int i = 0; i < SSZ; i++) {
            if (bits[i * 9 + w] & m) {
                float wv = A0[(size_t)(1 + order[DENS + i]) * PTOK + cj];
                ein[ptr] = i;
                ew[ptr]  = wv;
                alive[ptr] = (wv != 0.f) ? 1 : 0;
                ptr++;
            }
        }
    }

    // fixed-point pruning: m <- m & (avg[j] > avg[i])
    for (;;) {
        __syncthreads();
        {
            const int j = tid;
            int dg = 0; float s = 0.f;
            for (int e = offs[j]; e < offs[j + 1]; e++)
                if (alive[e]) { dg++; s += ew[e]; }
            degi[j] = dg;
            favg[j] = (dg > 0) ? (s / (float)dg) : 0.f;
        }
        if (tid == 0) changed = 0;
        __syncthreads();
        {
            const int j = tid;
            const float aj = favg[j];
            int ch = 0;
            for (int e = offs[j]; e < offs[j + 1]; e++)
                if (alive[e] && !(aj > favg[ein[e]])) { alive[e] = 0; ch = 1; }
            if (ch) atomicExch(&changed, 1);
        }
        __syncthreads();
        if (!changed) break;
    }

    // zero pruned weights
    {
        const int j = tid;
        for (int e = offs[j]; e < offs[j + 1]; e++)
            if (!alive[e]) ew[e] = 0.f;
    }

    // top-144 by in-degree (ties -> smaller index first)
    {
        const int j = tid;
        const int dj = degi[j];
        int r = 0;
        for (int q = 0; q < SSZ; q++) {
            int dq = degi[q];
            r += (dq > dj) || (dq == dj && q < j);
        }
        if (r < GSZ) gsel[r] = j;
    }
    __syncthreads();

    // ---- write scratch to global ----
    for (int e = tid; e < offs[SSZ]; e += 288) {
        g_ein[b][e] = 1 + order[DENS + ein[e]];   // resolve to tk row index
        g_ew[b][e]  = ew[e];
    }
    for (int g = tid; g < GSZ; g += 288) {
        int j = gsel[g];
        g_selrange[b][g][0] = offs[j];
        g_selrange[b][g][1] = offs[j + 1];
    }
    for (int u = tid; u < OUTROWS; u += 288) {
        int row;
        if (u == 0)            row = 0;
        else if (u <= DENS)    row = 1 + order[u - 1];
        else                   row = 1 + order[DENS + gsel[u - 1 - DENS]];
        g_rowmap[b][u] = row;
    }
    for (int v = tid; v < RCOLS; v += 288) {
        int c;
        if (v < DENS) c = order[v];
        else          c = order[DENS + gsel[v - DENS]];
        g_colmap[b][v] = c;
    }
}

// ---------------- kernel 2: out_tokens [B,433,768] ------------------------
__global__ __launch_bounds__(192) void k_tokens(const float* __restrict__ tk,
                                                float* __restrict__ out) {
    const int u = blockIdx.x;
    const int b = blockIdx.y;
    const int t = threadIdx.x;                   // 192 threads -> float4 over 768
    const float4* tk4 = (const float4*)tk;
    const int row = g_rowmap[b][u];
    float4 v = tk4[((size_t)b * NTOK + row) * (DIM / 4) + t];

    if (u > DENS) {                              // aggregated skip-selected rows
        const int g = u - 1 - DENS;
        const int st = g_selrange[b][g][0];
        const int en = g_selrange[b][g][1];
        float4 acc = make_float4(0.f, 0.f, 0.f, 0.f);
        for (int e = st; e < en; e++) {
            float w = g_ew[b][e];
            if (w != 0.f) {
                int sr = g_ein[b][e];
                float4 sv = tk4[((size_t)b * NTOK + sr) * (DIM / 4) + t];
                acc.x += w * sv.x; acc.y += w * sv.y;
                acc.z += w * sv.z; acc.w += w * sv.w;
            }
        }
        v.x = acc.x + v.x; v.y = acc.y + v.y;
        v.z = acc.z + v.z; v.w = acc.w + v.w;
    }
    ((float4*)out)[((size_t)b * OUTROWS + u) * (DIM / 4) + t] = v;
}

// ---------------- kernel 3: R [B,433,432] ----------------------------------
__global__ __launch_bounds__(192) void k_R(const float* __restrict__ attn,
                                           float* __restrict__ out) {
    __shared__ float srow[PTOK];
    __shared__ int   cmap[RCOLS];
    const int u = blockIdx.x;
    const int b = blockIdx.y;
    const int t = threadIdx.x;
    const int arow = g_rowmap[b][u];
    const float* src = attn + ((size_t)b * NTOK + arow) * PTOK;
    for (int p = t; p < PTOK; p += 192) srow[p] = src[p];
    for (int v = t; v < RCOLS; v += 192) cmap[v] = g_colmap[b][v];
    __syncthreads();
    float* dst = out + (size_t)BATCH * OUTROWS * DIM
                     + ((size_t)b * OUTROWS + u) * RCOLS;
    for (int v = t; v < RCOLS; v += 192) dst[v] = srow[cmap[v]];
}

// ---------------- launch ---------------------------------------------------
extern "C" void kernel_launch(void* const* d_in, const int* in_sizes, int n_in,
                              void* d_out, int out_size) {
    const float* tk   = (const float*)d_in[0];
    const float* attn = (const float*)d_in[1];
    float* out = (float*)d_out;

    k_order <<<BATCH, PTOK>>>(attn);
    k_top2  <<<dim3(SSZ / 4, BATCH), 128>>>(attn);
    k_graph2<<<BATCH, 288>>>(attn);
    k_tokens<<<dim3(OUTROWS, BATCH), 192>>>(tk, out);
    k_R     <<<dim3(OUTROWS, BATCH), 192>>>(attn, out);
}

// round 3
// speedup vs baseline: 2.0985x; 1.1544x over previous
#include <cuda_runtime.h>

#define BATCH  64
#define NTOK   577
#define PTOK   576      // patches
#define DENS   288      // kept dense tokens
#define SSZ    288      // skipped tokens
#define GSZ    144      // selected group size
#define DIM    768
#define OUTROWS 433     // 1 + DENS + GSZ
#define RCOLS  432      // DENS + GSZ
#define EMAX   1200     // <= 4*288 = 1152 edges max

// ---------------- scratch (device globals; no allocation) ----------------
__device__ int   g_order[BATCH][PTOK];          // argsort(-cls_attn)
__device__ int   g_t2[BATCH][SSZ][2];           // top-2 neighbor per skip row
__device__ int   g_rowmap[BATCH][OUTROWS];      // attention/tk row index per output row
__device__ int   g_colmap[BATCH][RCOLS];        // attention col index per R column
__device__ int   g_ein[BATCH][EMAX];            // tk row index of edge source (alive only)
__device__ float g_ew[BATCH][EMAX];             // edge weight (alive only)
__device__ int   g_selrange[BATCH][GSZ][2];     // compacted [start,end) per selected node

// ---------------- kernel A: argsort(-cls_attn), stable ---------------------
__global__ __launch_bounds__(PTOK) void k_order(const float* __restrict__ attn) {
    const int b = blockIdx.x;
    const int p = threadIdx.x;                  // one thread per element
    __shared__ float a[PTOK];
    __shared__ int   ord[PTOK];
    a[p] = attn[(size_t)b * NTOK * PTOK + p];
    __syncthreads();
    const float v = a[p];
    int r = 0;
    #pragma unroll 8
    for (int q = 0; q < PTOK; q++) {
        float u = a[q];
        r += (u > v) || (u == v && q < p);
    }
    ord[r] = p;
    __syncthreads();
    g_order[b][p] = ord[p];
}

// ---------------- kernel B: top-2 per skip row (1 warp per row) ------------
__global__ __launch_bounds__(128) void k_top2(const float* __restrict__ attn) {
    const int b    = blockIdx.y;
    const int warp = threadIdx.x >> 5;
    const int lane = threadIdx.x & 31;
    const int i    = blockIdx.x * 4 + warp;     // skip row index 0..287

    __shared__ int   ords[SSZ];
    __shared__ float rows[4][PTOK];

    for (int j = threadIdx.x; j < SSZ; j += 128) ords[j] = g_order[b][DENS + j];
    __syncthreads();

    const int ri = 1 + ords[i];
    const float* src = attn + ((size_t)b * NTOK + ri) * PTOK;
    for (int p = lane; p < PTOK; p += 32) rows[warp][p] = src[p];
    __syncwarp();

    // local top-2 with key = (monotone(value), 287-j): tie -> smaller j wins
    unsigned long long k1 = 0ull, k2 = 0ull;
    for (int j = lane; j < SSZ; j += 32) {
        if (j == i) continue;
        float v = rows[warp][ords[j]];
        unsigned ub = __float_as_uint(v);
        ub ^= (unsigned)(((int)ub >> 31)) | 0x80000000u;   // total order on floats
        unsigned long long key = ((unsigned long long)ub << 32) | (unsigned)(SSZ - 1 - j);
        if (key > k1)      { k2 = k1; k1 = key; }
        else if (key > k2) { k2 = key; }
    }
    #pragma unroll
    for (int off = 16; off > 0; off >>= 1) {
        unsigned long long o1 = __shfl_down_sync(0xffffffffu, k1, off);
        unsigned long long o2 = __shfl_down_sync(0xffffffffu, k2, off);
        if (o1 > k1) { k2 = (k1 > o2) ? k1 : o2; k1 = o1; }
        else         { k2 = (k2 > o1) ? k2 : o1; }
    }
    if (lane == 0) {
        g_t2[b][i][0] = SSZ - 1 - (int)(k1 & 0xffffffffu);
        g_t2[b][i][1] = SSZ - 1 - (int)(k2 & 0xffffffffu);
    }
}

// ---- parallel exclusive scan over 288 per-thread values (288 threads) -----
// offs[j] = sum of val over threads < j ; offs[SSZ] = total.
__device__ __forceinline__ void scan288(int tid, int v, int* offs, int* wsum) {
    const int lane = tid & 31, warp = tid >> 5;     // 9 warps
    int incl = v;
    #pragma unroll
    for (int off = 1; off < 32; off <<= 1) {
        int n = __shfl_up_sync(0xffffffffu, incl, off);
        if (lane >= off) incl += n;
    }
    if (lane == 31) wsum[warp] = incl;
    __syncthreads();
    if (tid == 0) {
        int acc = 0;
        #pragma unroll
        for (int w = 0; w < 9; w++) { int t = wsum[w]; wsum[w] = acc; acc += t; }
        offs[SSZ] = acc;
    }
    __syncthreads();
    offs[tid] = incl - v + wsum[warp];
    __syncthreads();
}

// ---------------- kernel C: symmetrize + CSR + prune + select --------------
__global__ __launch_bounds__(288) void k_graph2(const float* __restrict__ attn) {
    const int b   = blockIdx.x;
    const int tid = threadIdx.x;                 // 288 threads
    const float* A0 = attn + (size_t)b * NTOK * PTOK;

    __shared__ int   order[PTOK];
    __shared__ unsigned bits[SSZ * 9];           // 288x288 bit adjacency
    __shared__ int   offs[SSZ + 1];
    __shared__ int   coffs[SSZ + 1];
    __shared__ int   ein[EMAX];
    __shared__ float ew[EMAX];
    __shared__ unsigned char alive[EMAX];
    __shared__ float favg[SSZ];
    __shared__ int   degi[SSZ];
    __shared__ int   gsel[GSZ];
    __shared__ int   wsum[9];
    __shared__ int   changed;

    for (int p = tid; p < PTOK; p += 288) order[p] = g_order[b][p];
    for (int k = tid; k < SSZ * 9; k += 288) bits[k] = 0;
    __syncthreads();

    // symmetrize: bit(i,j) if j in top2(i) or i in top2(j)
    {
        const int i = tid;
        const int j1 = g_t2[b][i][0], j2 = g_t2[b][i][1];
        atomicOr(&bits[i * 9 + (j1 >> 5)], 1u << (j1 & 31));
        atomicOr(&bits[i * 9 + (j2 >> 5)], 1u << (j2 & 31));
        atomicOr(&bits[j1 * 9 + (i >> 5)], 1u << (i & 31));
        atomicOr(&bits[j2 * 9 + (i >> 5)], 1u << (i & 31));
    }
    __syncthreads();

    // incoming-degree counts per column j, then exclusive scan
    int mycnt;
    {
        const int j = tid;
        const unsigned m = 1u << (j & 31);
        const int w = j >> 5;
        int c = 0;
        for (int i = 0; i < SSZ; i++) c += (bits[i * 9 + w] & m) ? 1 : 0;
        mycnt = c;
    }
    __syncthreads();
    scan288(tid, mycnt, offs, wsum);

    // fill incoming CSR (i ascending within each j). M = (W != 0)
    {
        const int j = tid;
        const unsigned m = 1u << (j & 31);
        const int w = j >> 5;
        const int cj = order[DENS + j];
        int ptr = offs[j];
        for (int i = 0; i < SSZ; i++) {
            if (bits[i * 9 + w] & m) {
                float wv = A0[(size_t)(1 + order[DENS + i]) * PTOK + cj];
                ein[ptr] = i;
                ew[ptr]  = wv;
                alive[ptr] = (wv != 0.f) ? 1 : 0;
                ptr++;
            }
        }
    }

    // fixed-point pruning: m <- m & (avg[j] > avg[i])
    for (;;) {
        __syncthreads();
        {
            const int j = tid;
            int dg = 0; float s = 0.f;
            for (int e = offs[j]; e < offs[j + 1]; e++)
                if (alive[e]) { dg++; s += ew[e]; }
            degi[j] = dg;
            favg[j] = (dg > 0) ? (s / (float)dg) : 0.f;
        }
        if (tid == 0) changed = 0;
        __syncthreads();
        {
            const int j = tid;
            const float aj = favg[j];
            int ch = 0;
            for (int e = offs[j]; e < offs[j + 1]; e++)
                if (alive[e] && !(aj > favg[ein[e]])) { alive[e] = 0; ch = 1; }
            if (ch) atomicExch(&changed, 1);
        }
        __syncthreads();
        if (!changed) break;
    }
    // degi[j] now equals the final alive in-degree (last iter removed nothing)

    // compacted offsets over final degrees
    scan288(tid, degi[tid], coffs, wsum);

    // top-144 by in-degree (ties -> smaller index first)
    {
        const int j = tid;
        const int dj = degi[j];
        int r = 0;
        for (int q = 0; q < SSZ; q++) {
            int dq = degi[q];
            r += (dq > dj) || (dq == dj && q < j);
        }
        if (r < GSZ) gsel[r] = j;
    }

    // ---- write compacted alive edges to global (tk-row-resolved) ----
    {
        const int j = tid;
        int ptr = coffs[j];
        for (int e = offs[j]; e < offs[j + 1]; e++) {
            if (alive[e]) {
                g_ein[b][ptr] = 1 + order[DENS + ein[e]];
                g_ew[b][ptr]  = ew[e];
                ptr++;
            }
        }
    }
    __syncthreads();

    for (int g = tid; g < GSZ; g += 288) {
        int j = gsel[g];
        g_selrange[b][g][0] = coffs[j];
        g_selrange[b][g][1] = coffs[j] + degi[j];
    }
    for (int u = tid; u < OUTROWS; u += 288) {
        int row;
        if (u == 0)            row = 0;
        else if (u <= DENS)    row = 1 + order[u - 1];
        else                   row = 1 + order[DENS + gsel[u - 1 - DENS]];
        g_rowmap[b][u] = row;
    }
    for (int v = tid; v < RCOLS; v += 288) {
        int c;
        if (v < DENS) c = order[v];
        else          c = order[DENS + gsel[v - DENS]];
        g_colmap[b][v] = c;
    }
}

// -------- fused output kernel: out_tokens [B,433,768] + R [B,433,432] ------
__global__ __launch_bounds__(192) void k_out(const float* __restrict__ tk,
                                             const float* __restrict__ attn,
                                             float* __restrict__ out) {
    __shared__ float srow[PTOK];
    __shared__ int   cmap[RCOLS];
    const int u = blockIdx.x;
    const int b = blockIdx.y;
    const int t = threadIdx.x;                   // 192 threads
    const int row = g_rowmap[b][u];

    // stage the attention row + column map early (overlaps token latency chain)
    const float* asrc = attn + ((size_t)b * NTOK + row) * PTOK;
    for (int p = t; p < PTOK; p += 192) srow[p] = asrc[p];
    for (int v2 = t; v2 < RCOLS; v2 += 192) cmap[v2] = g_colmap[b][v2];

    // ---- tokens: one float4 per thread ----
    const float4* tk4 = (const float4*)tk;
    float4 v = tk4[((size_t)b * NTOK + row) * (DIM / 4) + t];
    if (u > DENS) {                              // aggregated skip-selected rows
        const int g = u - 1 - DENS;
        const int st = g_selrange[b][g][0];
        const int en = g_selrange[b][g][1];
        float4 acc = make_float4(0.f, 0.f, 0.f, 0.f);
        for (int e = st; e < en; e++) {          // alive-only, branch-free body
            float w  = g_ew[b][e];
            int   sr = g_ein[b][e];
            float4 sv = tk4[((size_t)b * NTOK + sr) * (DIM / 4) + t];
            acc.x += w * sv.x; acc.y += w * sv.y;
            acc.z += w * sv.z; acc.w += w * sv.w;
        }
        v.x = acc.x + v.x; v.y = acc.y + v.y;
        v.z = acc.z + v.z; v.w = acc.w + v.w;
    }
    ((float4*)out)[((size_t)b * OUTROWS + u) * (DIM / 4) + t] = v;

    // ---- R row ----
    __syncthreads();
    float* dst = out + (size_t)BATCH * OUTROWS * DIM
                     + ((size_t)b * OUTROWS + u) * RCOLS;
    for (int v2 = t; v2 < RCOLS; v2 += 192) dst[v2] = srow[cmap[v2]];
}

// ---------------- launch ---------------------------------------------------
extern "C" void kernel_launch(void* const* d_in, const int* in_sizes, int n_in,
                              void* d_out, int out_size) {
    const float* tk   = (const float*)d_in[0];
    const float* attn = (const float*)d_in[1];
    float* out = (float*)d_out;

    k_order <<<BATCH, PTOK>>>(attn);
    k_top2  <<<dim3(SSZ / 4, BATCH), 128>>>(attn);
    k_graph2<<<BATCH, 288>>>(attn);
    k_out   <<<dim3(OUTROWS, BATCH), 192>>>(tk, attn, out);
}